// round 2
// baseline (speedup 1.0000x reference)
#include <cuda_runtime.h>
#include <math.h>
#include <stdint.h>

// Problem shape (fixed by dataset): CRF loss, L=512 seq, B=512 batch, T=128 tags.
#define LL 512
#define BB 512
#define TT 128
#define NB 4            // batches per CTA
#define NCTA (BB/NB)    // 128 CTAs
#define NTHREADS 256
#define NWARP 8
#define JPW (TT/NWARP)  // 16 j per warp

// Deterministic per-batch scratch (device globals: no allocation).
__device__ float g_logZ[BB];
__device__ float g_num[BB];

// Dynamic SMEM layout (floats):
//   sE    [0      , 16384)   exp(transitions)  64 KB
//   sP    [16384  , 17408)   two ping-pong p buffers of 512 ( [k][b] layout )
//   sPart [17408  , 21504)   partials [warp][b][k]  16 KB
//   sS    [21504  , 21512)   per-batch half sums
#define SM_FLOATS 21520
#define SM_BYTES  (SM_FLOATS * 4)

__global__ __launch_bounds__(NTHREADS, 1)
void crf_forward(const float* __restrict__ emissions,
                 const int* __restrict__ mask,        // bool delivered as int32
                 const float* __restrict__ start_t,
                 const float* __restrict__ end_t,
                 const float* __restrict__ trans)
{
    extern __shared__ float sm[];
    float* sE    = sm;
    float* sP    = sm + 16384;
    float* sPart = sm + 17408;
    float* sS    = sm + 21504;

    const int tid  = threadIdx.x;
    const int w    = tid >> 5;
    const int lane = tid & 31;
    const int b0   = blockIdx.x * NB;

    // E = exp(transitions), row-major [j][k]
    #pragma unroll 4
    for (int i = tid; i < TT * TT; i += NTHREADS)
        sE[i] = __expf(trans[i]);

    // epilogue mapping: thread owns (batch eb, tags ek and ek+1)
    const int eb = tid >> 6;          // 0..3
    const int ek = (tid & 63) << 1;   // 0,2,...,126

    // init p (buffer 0): p[k][b] = exp(start[k] + emissions[0,b,k])
    {
        const float* em0 = emissions + ((size_t)(b0 + eb)) * TT + ek;
        float e0 = em0[0], e1 = em0[1];
        sP[ek * NB + eb]       = __expf(start_t[ek]     + e0);
        sP[(ek + 1) * NB + eb] = __expf(start_t[ek + 1] + e1);
    }
    __syncthreads();

    int e_acc = 0;      // power-of-two log-scale (only meaningful on tid&63==0)
    int ping  = 0;

    const int jbase = w * JPW;
    const int kq    = lane << 2;

    for (int i = 1; i < LL; ++i) {
        float* Pin  = sP + ping;
        float* Pout = sP + (512 - ping);

        // prefetch this step's emissions + mask (hidden under FMA phase)
        const float* emp = emissions + ((size_t)i * BB + (b0 + eb)) * TT + ek;
        float em0 = emp[0], em1 = emp[1];
        int m = mask[i * BB + b0 + eb];

        // ---- FMA phase: warp w reduces j in [jbase, jbase+16) for all 4 batches
        float4 a0 = {0,0,0,0}, a1 = {0,0,0,0}, a2 = {0,0,0,0}, a3 = {0,0,0,0};
        #pragma unroll
        for (int jj = 0; jj < JPW; ++jj) {
            const int j = jbase + jj;
            float4 pv = *reinterpret_cast<const float4*>(Pin + (j << 2));       // broadcast
            float4 ev = *reinterpret_cast<const float4*>(sE + (j << 7) + kq);
            a0.x += pv.x * ev.x; a0.y += pv.x * ev.y; a0.z += pv.x * ev.z; a0.w += pv.x * ev.w;
            a1.x += pv.y * ev.x; a1.y += pv.y * ev.y; a1.z += pv.y * ev.z; a1.w += pv.y * ev.w;
            a2.x += pv.z * ev.x; a2.y += pv.z * ev.y; a2.z += pv.z * ev.z; a2.w += pv.z * ev.w;
            a3.x += pv.w * ev.x; a3.y += pv.w * ev.y; a3.z += pv.w * ev.z; a3.w += pv.w * ev.w;
        }
        *reinterpret_cast<float4*>(sPart + (((w << 2) + 0) << 7) + kq) = a0;
        *reinterpret_cast<float4*>(sPart + (((w << 2) + 1) << 7) + kq) = a1;
        *reinterpret_cast<float4*>(sPart + (((w << 2) + 2) << 7) + kq) = a2;
        *reinterpret_cast<float4*>(sPart + (((w << 2) + 3) << 7) + kq) = a3;
        __syncthreads();

        // ---- reduce 8 warp-partials, apply exp(emissions)
        float vx = 0.f, vy = 0.f;
        #pragma unroll
        for (int ww = 0; ww < NWARP; ++ww) {
            float2 pw = *reinterpret_cast<const float2*>(sPart + (((ww << 2) + eb) << 7) + ek);
            vx += pw.x; vy += pw.y;
        }
        float q0 = vx * __expf(em0);
        float q1 = vy * __expf(em1);

        float loc = q0 + q1;
        #pragma unroll
        for (int off = 16; off; off >>= 1)
            loc += __shfl_xor_sync(0xffffffffu, loc, off);
        if (lane == 0) sS[(eb << 1) + (w & 1)] = loc;
        __syncthreads();

        // ---- exact power-of-two renormalization
        float s = sS[eb << 1] + sS[(eb << 1) + 1];
        int   e = ((__float_as_int(s) >> 23) & 255) - 126;   // s * 2^-e in [0.5, 1)
        float scale = __int_as_float((127 - e) << 23);        // exact 2^-e
        if (m) {
            Pout[ek * NB + eb]       = q0 * scale;
            Pout[(ek + 1) * NB + eb] = q1 * scale;
            if ((tid & 63) == 0) e_acc += e;
        } else {
            Pout[ek * NB + eb]       = Pin[ek * NB + eb];
            Pout[(ek + 1) * NB + eb] = Pin[(ek + 1) * NB + eb];
        }
        __syncthreads();
        ping = 512 - ping;
    }

    // ---- finalize: logZ_b = e_acc*ln2 + log( sum_k p[k] * exp(end[k]) )
    {
        float* Pin = sP + ping;
        float z = Pin[ek * NB + eb]       * __expf(end_t[ek])
                + Pin[(ek + 1) * NB + eb] * __expf(end_t[ek + 1]);
        #pragma unroll
        for (int off = 16; off; off >>= 1)
            z += __shfl_xor_sync(0xffffffffu, z, off);
        if (lane == 0) sS[(eb << 1) + (w & 1)] = z;
        __syncthreads();
        if ((tid & 63) == 0) {
            float s = sS[eb << 1] + sS[(eb << 1) + 1];
            g_logZ[b0 + eb] = (float)e_acc * 0.6931471805599453f + logf(s);
        }
    }
}

// Numerator: one block per batch. scores = emissions at gold tags (+ transition
// scores for i>0), masked; plus unmasked start[tags[0]] and end[tags[ends]].
__global__ void crf_num(const float* __restrict__ emissions,
                        const int*   __restrict__ tags,
                        const int*   __restrict__ mask,   // bool delivered as int32
                        const float* __restrict__ start_t,
                        const float* __restrict__ end_t,
                        const float* __restrict__ trans)
{
    const int b   = blockIdx.x;
    const int tid = threadIdx.x;
    __shared__ float rf[256];
    __shared__ int   ri[256];

    float loc = 0.f;
    int   cnt = 0;
    for (int i = tid; i < LL; i += 256) {
        int tag = tags[i * BB + b];
        int m = mask[i * BB + b];
        if (m) {
            loc += emissions[((size_t)i * BB + b) * TT + tag];
            cnt++;
            if (i > 0)
                loc += trans[tags[(i - 1) * BB + b] * TT + tag];
        }
        if (i == 0)
            loc += start_t[tag];
    }
    rf[tid] = loc; ri[tid] = cnt;
    __syncthreads();
    #pragma unroll
    for (int s = 128; s > 0; s >>= 1) {
        if (tid < s) { rf[tid] += rf[tid + s]; ri[tid] += ri[tid + s]; }
        __syncthreads();
    }
    if (tid == 0) {
        int ends = ri[0] - 1;
        if (ends < 0) ends = 0;
        int last_tag = tags[ends * BB + b];
        g_num[b] = rf[0] + end_t[last_tag];
    }
}

// Final deterministic combine: out = (sum_b logZ_b - sum_b num_b) / B
__global__ void crf_final(float* __restrict__ out)
{
    __shared__ float r[512];
    const int tid = threadIdx.x;
    r[tid] = g_logZ[tid] - g_num[tid];
    __syncthreads();
    #pragma unroll
    for (int s = 256; s > 0; s >>= 1) {
        if (tid < s) r[tid] += r[tid + s];
        __syncthreads();
    }
    if (tid == 0) out[0] = r[0] * (1.0f / (float)BB);
}

extern "C" void kernel_launch(void* const* d_in, const int* in_sizes, int n_in,
                              void* d_out, int out_size)
{
    const float* emissions = (const float*)d_in[0];
    const int*   tags      = (const int*)d_in[1];
    const int*   mask      = (const int*)d_in[2];
    const float* start_t   = (const float*)d_in[3];
    const float* end_t     = (const float*)d_in[4];
    const float* trans     = (const float*)d_in[5];
    float*       out       = (float*)d_out;

    cudaFuncSetAttribute(crf_forward, cudaFuncAttributeMaxDynamicSharedMemorySize, SM_BYTES);

    crf_forward<<<NCTA, NTHREADS, SM_BYTES>>>(emissions, mask, start_t, end_t, trans);
    crf_num<<<BB, 256>>>(emissions, tags, mask, start_t, end_t, trans);
    crf_final<<<1, BB>>>(out);
}

// round 3
// speedup vs baseline: 1.1041x; 1.1041x over previous
#include <cuda_runtime.h>
#include <math.h>
#include <stdint.h>

// CRF loss: L=512 seq, B=512 batch, T=128 tags.
#define LL 512
#define BB 512
#define TT 128
#define NB 4
#define NCTA (BB/NB)      // 128 CTAs
#define NTHREADS 256
#define PSTRIDE 144       // per-batch alpha row: 4 jo-blocks of 36 floats (pad kills bank conflicts)
#define LN2F 0.6931471805599453f

__device__ float g_logZ[BB];
__device__ float g_num[BB];

union F4U { float4 v; struct { unsigned long long p01, p23; } u; };

__device__ __forceinline__ unsigned long long ffma2(unsigned long long a,
                                                    unsigned long long b,
                                                    unsigned long long c) {
    unsigned long long d;
    asm("fma.rn.f32x2 %0, %1, %2, %3;" : "=l"(d) : "l"(a), "l"(b), "l"(c));
    return d;
}
__device__ __forceinline__ unsigned long long packf2(float lo, float hi) {
    unsigned long long r;
    asm("mov.b64 %0, {%1,%2};" : "=l"(r) : "f"(lo), "f"(hi));
    return r;
}
__device__ __forceinline__ float2 unpackf2(unsigned long long v) {
    float2 f;
    asm("mov.b64 {%0,%1}, %2;" : "=f"(f.x), "=f"(f.y) : "l"(v));
    return f;
}

__global__ __launch_bounds__(NTHREADS, 1)
void crf_forward(const float* __restrict__ emissions,
                 const int* __restrict__ mask,
                 const float* __restrict__ start_t,
                 const float* __restrict__ end_t,
                 const float* __restrict__ trans)
{
    // E blobs: per (smem-iter t, thread) 16B = 4 j-consecutive E values for one k.
    __shared__ __align__(16) float4 blobA[4 * NTHREADS];   // k0 column
    __shared__ __align__(16) float4 blobB[4 * NTHREADS];   // k1 column
    __shared__ __align__(16) float  sP[2][NB * PSTRIDE];   // alpha ping-pong, layout [b][j padded]
    __shared__ __align__(16) float  sS[2][NB][8];          // per-warp normalization partials

    const int tid  = threadIdx.x;
    const int w    = tid >> 5;
    const int lane = tid & 31;
    const int jo   = lane >> 3;        // j-quarter 0..3 ; also the batch this lane finalizes
    const int kidx = lane & 7;
    const int k0   = w * 16 + kidx * 2;
    const int bg   = blockIdx.x * NB + jo;
    const int ka   = jo * PSTRIDE + (k0 >> 5) * 36 + (k0 & 31);  // alpha addr of (b=jo, k0)

    // ---------- setup: E = exp(transitions), split register-half / smem-blob-half ----------
    unsigned long long eReg[2][8];   // [k0/k1][j-pair 0..7] for j in [jo*32, jo*32+16)
    #pragma unroll
    for (int t = 0; t < 4; ++t) {
        int j = jo * 32 + t * 4;
        float a0 = __expf(trans[(j + 0) * TT + k0]);
        float a1 = __expf(trans[(j + 1) * TT + k0]);
        float a2 = __expf(trans[(j + 2) * TT + k0]);
        float a3 = __expf(trans[(j + 3) * TT + k0]);
        eReg[0][2 * t]     = packf2(a0, a1);
        eReg[0][2 * t + 1] = packf2(a2, a3);
        float c0 = __expf(trans[(j + 0) * TT + k0 + 1]);
        float c1 = __expf(trans[(j + 1) * TT + k0 + 1]);
        float c2 = __expf(trans[(j + 2) * TT + k0 + 1]);
        float c3 = __expf(trans[(j + 3) * TT + k0 + 1]);
        eReg[1][2 * t]     = packf2(c0, c1);
        eReg[1][2 * t + 1] = packf2(c2, c3);

        int js = j + 16;
        blobA[t * NTHREADS + tid] = make_float4(__expf(trans[(js + 0) * TT + k0]),
                                                __expf(trans[(js + 1) * TT + k0]),
                                                __expf(trans[(js + 2) * TT + k0]),
                                                __expf(trans[(js + 3) * TT + k0]));
        blobB[t * NTHREADS + tid] = make_float4(__expf(trans[(js + 0) * TT + k0 + 1]),
                                                __expf(trans[(js + 1) * TT + k0 + 1]),
                                                __expf(trans[(js + 2) * TT + k0 + 1]),
                                                __expf(trans[(js + 3) * TT + k0 + 1]));
    }

    // ---------- init: p~0 = exp(start + emissions[0]) ----------
    {
        const float2 em = *(const float2*)(emissions + (size_t)bg * TT + k0);
        const float2 st = *(const float2*)(start_t + k0);
        float v0 = __expf(st.x + em.x);
        float v1 = __expf(st.y + em.y);
        *(float2*)&sP[0][ka] = make_float2(v0, v1);
        float pr = v0 + v1;
        pr += __shfl_xor_sync(0xffffffffu, pr, 1);
        pr += __shfl_xor_sync(0xffffffffu, pr, 2);
        pr += __shfl_xor_sync(0xffffffffu, pr, 4);
        if (kidx == 0) sS[0][jo][w] = pr;
    }
    __syncthreads();

    int cur = 0;
    int e_acc = 0;

    // ---------- main recursion: ONE sync per step ----------
    for (int i = 1; i < LL; ++i) {
        const float* Pin  = sP[cur];
        float*       Pout = sP[cur ^ 1];

        // prefetch global + small smem reads (consumed late; hidden under FMA)
        const float2 em   = *(const float2*)(emissions + ((size_t)i * BB + bg) * TT + k0);
        const int    m    = mask[i * BB + bg];
        const float2 oldp = *(const float2*)&Pin[ka];
        const float4 s4a  = *(const float4*)&sS[cur][jo][0];
        const float4 s4b  = *(const float4*)&sS[cur][jo][4];

        // pending scale from previous step (exact power of two)
        float s = ((s4a.x + s4a.y) + (s4a.z + s4a.w)) + ((s4b.x + s4b.y) + (s4b.z + s4b.w));
        int   e = ((__float_as_int(s) >> 23) & 255) - 126;      // s*2^-e in [0.5,1)
        float scale = __int_as_float((127 - e) << 23);

        // j-contraction over this lane's quarter, 4 batches, 2 k-columns
        unsigned long long acc[2][4];
        #pragma unroll
        for (int kk = 0; kk < 2; ++kk)
            #pragma unroll
            for (int b = 0; b < 4; ++b) acc[kk][b] = 0ull;

        const float* pb = Pin + jo * 36;
        #pragma unroll
        for (int t = 0; t < 4; ++t) {           // register-E half (j-local 0..15)
            #pragma unroll
            for (int b = 0; b < 4; ++b) {
                F4U pv; pv.v = *(const float4*)(pb + b * PSTRIDE + t * 4);
                acc[0][b] = ffma2(pv.u.p01, eReg[0][2 * t],     acc[0][b]);
                acc[0][b] = ffma2(pv.u.p23, eReg[0][2 * t + 1], acc[0][b]);
                acc[1][b] = ffma2(pv.u.p01, eReg[1][2 * t],     acc[1][b]);
                acc[1][b] = ffma2(pv.u.p23, eReg[1][2 * t + 1], acc[1][b]);
            }
        }
        #pragma unroll
        for (int t = 0; t < 4; ++t) {           // smem-E half (j-local 16..31)
            F4U eA; eA.v = blobA[t * NTHREADS + tid];
            F4U eB; eB.v = blobB[t * NTHREADS + tid];
            #pragma unroll
            for (int b = 0; b < 4; ++b) {
                F4U pv; pv.v = *(const float4*)(pb + b * PSTRIDE + 16 + t * 4);
                acc[0][b] = ffma2(pv.u.p01, eA.u.p01, acc[0][b]);
                acc[0][b] = ffma2(pv.u.p23, eA.u.p23, acc[0][b]);
                acc[1][b] = ffma2(pv.u.p01, eB.u.p01, acc[1][b]);
                acc[1][b] = ffma2(pv.u.p23, eB.u.p23, acc[1][b]);
            }
        }

        // horizontal add + reduce over jo quarters (lanes ^8, ^16)
        float qA[4], qB[4];
        #pragma unroll
        for (int b = 0; b < 4; ++b) {
            float2 fa = unpackf2(acc[0][b]); qA[b] = fa.x + fa.y;
            float2 fb = unpackf2(acc[1][b]); qB[b] = fb.x + fb.y;
        }
        #pragma unroll
        for (int b = 0; b < 4; ++b) {
            qA[b] += __shfl_xor_sync(0xffffffffu, qA[b], 8);
            qA[b] += __shfl_xor_sync(0xffffffffu, qA[b], 16);
            qB[b] += __shfl_xor_sync(0xffffffffu, qB[b], 8);
            qB[b] += __shfl_xor_sync(0xffffffffu, qB[b], 16);
        }
        // lane takes its own batch (b == jo)
        float qq0 = (jo == 0) ? qA[0] : (jo == 1) ? qA[1] : (jo == 2) ? qA[2] : qA[3];
        float qq1 = (jo == 0) ? qB[0] : (jo == 1) ? qB[1] : (jo == 2) ? qB[2] : qB[3];

        float f0 = __expf(em.x) * scale;
        float f1 = __expf(em.y) * scale;
        float qs0, qs1;
        if (m) { qs0 = qq0 * f0; qs1 = qq1 * f1; e_acc += e; }
        else   { qs0 = oldp.x;   qs1 = oldp.y; }

        *(float2*)&Pout[ka] = make_float2(qs0, qs1);

        float pr = qs0 + qs1;
        pr += __shfl_xor_sync(0xffffffffu, pr, 1);
        pr += __shfl_xor_sync(0xffffffffu, pr, 2);
        pr += __shfl_xor_sync(0xffffffffu, pr, 4);
        if (kidx == 0) sS[cur ^ 1][jo][w] = pr;

        __syncthreads();
        cur ^= 1;
    }

    // ---------- finalize: logZ = e_acc*ln2 + log( sum_k p~[k]*exp(end[k]) ) ----------
    {
        const float* Pin = sP[cur];
        const float2 en  = *(const float2*)(end_t + k0);
        const float2 pv  = *(const float2*)&Pin[ka];
        float z = pv.x * __expf(en.x) + pv.y * __expf(en.y);
        z += __shfl_xor_sync(0xffffffffu, z, 1);
        z += __shfl_xor_sync(0xffffffffu, z, 2);
        z += __shfl_xor_sync(0xffffffffu, z, 4);
        if (kidx == 0) sS[0][jo][w] = z;
        __syncthreads();
        if (w == 0 && kidx == 0) {
            float tot = 0.f;
            #pragma unroll
            for (int ww = 0; ww < 8; ++ww) tot += sS[0][jo][ww];
            g_logZ[bg] = (float)e_acc * LN2F + logf(tot);
        }
    }
}

// Numerator: one block per batch.
__global__ void crf_num(const float* __restrict__ emissions,
                        const int*   __restrict__ tags,
                        const int*   __restrict__ mask,
                        const float* __restrict__ start_t,
                        const float* __restrict__ end_t,
                        const float* __restrict__ trans)
{
    const int b   = blockIdx.x;
    const int tid = threadIdx.x;
    __shared__ float rf[256];
    __shared__ int   ri[256];

    float loc = 0.f;
    int   cnt = 0;
    for (int i = tid; i < LL; i += 256) {
        int tag = tags[i * BB + b];
        int m   = mask[i * BB + b];
        if (m) {
            loc += emissions[((size_t)i * BB + b) * TT + tag];
            cnt++;
            if (i > 0) loc += trans[tags[(i - 1) * BB + b] * TT + tag];
        }
        if (i == 0) loc += start_t[tag];
    }
    rf[tid] = loc; ri[tid] = cnt;
    __syncthreads();
    #pragma unroll
    for (int s = 128; s > 0; s >>= 1) {
        if (tid < s) { rf[tid] += rf[tid + s]; ri[tid] += ri[tid + s]; }
        __syncthreads();
    }
    if (tid == 0) {
        int ends = ri[0] - 1;
        if (ends < 0) ends = 0;
        g_num[b] = rf[0] + end_t[tags[ends * BB + b]];
    }
}

__global__ void crf_final(float* __restrict__ out)
{
    __shared__ float r[512];
    const int tid = threadIdx.x;
    r[tid] = g_logZ[tid] - g_num[tid];
    __syncthreads();
    #pragma unroll
    for (int s = 256; s > 0; s >>= 1) {
        if (tid < s) r[tid] += r[tid + s];
        __syncthreads();
    }
    if (tid == 0) out[0] = r[0] * (1.0f / (float)BB);
}

extern "C" void kernel_launch(void* const* d_in, const int* in_sizes, int n_in,
                              void* d_out, int out_size)
{
    const float* emissions = (const float*)d_in[0];
    const int*   tags      = (const int*)d_in[1];
    const int*   mask      = (const int*)d_in[2];
    const float* start_t   = (const float*)d_in[3];
    const float* end_t     = (const float*)d_in[4];
    const float* trans     = (const float*)d_in[5];
    float*       out       = (float*)d_out;

    crf_forward<<<NCTA, NTHREADS>>>(emissions, mask, start_t, end_t, trans);
    crf_num<<<BB, 256>>>(emissions, tags, mask, start_t, end_t, trans);
    crf_final<<<1, BB>>>(out);
}

// round 4
// speedup vs baseline: 1.2600x; 1.1412x over previous
#include <cuda_runtime.h>
#include <math.h>
#include <stdint.h>

// CRF loss: L=512 seq, B=512 batch, T=128 tags.
#define LL 512
#define BB 512
#define TT 128
#define NB 4              // batches per CTA (2 groups x 2)
#define NCTA (BB/NB)      // 128 CTAs, 1 per SM
#define NTHREADS 256
#define LN2F 0.6931471805599453f

__device__ float g_logZ[BB];
__device__ float g_num[BB];

union F4U { float4 v; struct { unsigned long long p01, p23; } u; };

__device__ __forceinline__ unsigned long long ffma2(unsigned long long a,
                                                    unsigned long long b,
                                                    unsigned long long c) {
    unsigned long long d;
    asm("fma.rn.f32x2 %0, %1, %2, %3;" : "=l"(d) : "l"(a), "l"(b), "l"(c));
    return d;
}
__device__ __forceinline__ unsigned long long packf2(float lo, float hi) {
    unsigned long long r;
    asm("mov.b64 %0, {%1,%2};" : "=l"(r) : "f"(lo), "f"(hi));
    return r;
}
__device__ __forceinline__ float2 unpackf2(unsigned long long v) {
    float2 f;
    asm("mov.b64 {%0,%1}, %2;" : "=f"(f.x), "=f"(f.y) : "l"(v));
    return f;
}
__device__ __forceinline__ void barg(int g) {   // named barrier per 128-thread group
    asm volatile("bar.sync %0, 128;" :: "r"(g + 1));
}

// Thread org (per CTA): group g = w>>2 (2 batches each), wg = w&3 covers k-range
// [wg*32, wg*32+32); lane: jo = lane>>4 (j-half of 64), kidx = lane&15 → k0.
// Each lane: 64 j x 2 k x 2 b = 256 MACs = 128 FFMA2/step. E register-resident.
__global__ __launch_bounds__(NTHREADS, 1)
void crf_forward(const float* __restrict__ emissions,
                 const int* __restrict__ mask,
                 const float* __restrict__ start_t,
                 const float* __restrict__ end_t,
                 const float* __restrict__ trans)
{
    __shared__ __align__(16) float sP[2][2][2][TT];   // [ping][g][b][k]
    __shared__ __align__(16) float sS[2][2][2][4];    // [ping][g][b][wg] partials

    const int tid  = threadIdx.x;
    const int w    = tid >> 5;
    const int lane = tid & 31;
    const int g    = w >> 2;
    const int wg   = w & 3;
    const int jo   = lane >> 4;       // j-half; also this lane's epilogue batch (local)
    const int kidx = lane & 15;
    const int k0   = wg * 32 + kidx * 2;
    const int bg   = blockIdx.x * NB + g * 2 + jo;    // global batch this lane finalizes

    // ---- E = exp(transitions), fully in registers: 64 j x 2 k per lane ----
    unsigned long long eR[16][2][2];  // [t][sub jpair][k0/k1]
    #pragma unroll
    for (int t = 0; t < 16; ++t) {
        #pragma unroll
        for (int sub = 0; sub < 2; ++sub) {
            int j = jo * 64 + t * 4 + sub * 2;
            eR[t][sub][0] = packf2(__expf(trans[j * TT + k0]),
                                   __expf(trans[(j + 1) * TT + k0]));
            eR[t][sub][1] = packf2(__expf(trans[j * TT + k0 + 1]),
                                   __expf(trans[(j + 1) * TT + k0 + 1]));
        }
    }

    // ---- init: p~0 = exp(start + emissions[0]) for batch (g, jo) ----
    {
        const float2 em = *(const float2*)(emissions + (size_t)bg * TT + k0);
        const float2 st = *(const float2*)(start_t + k0);
        float v0 = __expf(st.x + em.x);
        float v1 = __expf(st.y + em.y);
        *(float2*)&sP[0][g][jo][k0] = make_float2(v0, v1);
        float pr = v0 + v1;
        pr += __shfl_xor_sync(0xffffffffu, pr, 1);
        pr += __shfl_xor_sync(0xffffffffu, pr, 2);
        pr += __shfl_xor_sync(0xffffffffu, pr, 4);
        pr += __shfl_xor_sync(0xffffffffu, pr, 8);
        if (kidx == 0) sS[0][g][jo][wg] = pr;
    }
    __syncthreads();

    int cur = 0;
    int e_acc = 0;

    for (int i = 1; i < LL; ++i) {
        const float* P0 = &sP[cur][g][0][0];
        const float* P1 = &sP[cur][g][1][0];

        // prefetch (consumed late, hidden under FMA)
        const float2 em   = *(const float2*)(emissions + ((size_t)i * BB + bg) * TT + k0);
        const int    m    = mask[i * BB + bg];
        const float2 oldp = *(const float2*)&sP[cur][g][jo][k0];
        const float4 sv   = *(const float4*)&sS[cur][g][jo][0];

        // pending exact power-of-two scale from previous step's sums
        float s = (sv.x + sv.y) + (sv.z + sv.w);
        int   e = ((__float_as_int(s) >> 23) & 255) - 126;    // s*2^-e in [0.5,1)
        float scale = __int_as_float((127 - e) << 23);

        // ---- j-contraction: acc[b][k] over this lane's 64-j half ----
        unsigned long long acc00 = 0, acc01 = 0, acc10 = 0, acc11 = 0;
        const int jb = jo * 64;
        #pragma unroll
        for (int t = 0; t < 16; ++t) {
            F4U p0; p0.v = *(const float4*)(P0 + jb + t * 4);   // broadcast loads
            F4U p1; p1.v = *(const float4*)(P1 + jb + t * 4);
            acc00 = ffma2(p0.u.p01, eR[t][0][0], acc00);
            acc01 = ffma2(p0.u.p01, eR[t][0][1], acc01);
            acc10 = ffma2(p1.u.p01, eR[t][0][0], acc10);
            acc11 = ffma2(p1.u.p01, eR[t][0][1], acc11);
            acc00 = ffma2(p0.u.p23, eR[t][1][0], acc00);
            acc01 = ffma2(p0.u.p23, eR[t][1][1], acc01);
            acc10 = ffma2(p1.u.p23, eR[t][1][0], acc10);
            acc11 = ffma2(p1.u.p23, eR[t][1][1], acc11);
        }

        // horizontal add + cross-jo reduce (one shfl per value)
        float2 h;
        h = unpackf2(acc00); float f00 = h.x + h.y;
        h = unpackf2(acc01); float f01 = h.x + h.y;
        h = unpackf2(acc10); float f10 = h.x + h.y;
        h = unpackf2(acc11); float f11 = h.x + h.y;
        f00 += __shfl_xor_sync(0xffffffffu, f00, 16);
        f01 += __shfl_xor_sync(0xffffffffu, f01, 16);
        f10 += __shfl_xor_sync(0xffffffffu, f10, 16);
        f11 += __shfl_xor_sync(0xffffffffu, f11, 16);

        // lane keeps its own batch (local b == jo)
        float q0 = (jo == 0) ? f00 : f10;
        float q1 = (jo == 0) ? f01 : f11;

        float qs0, qs1;
        if (m) {
            qs0 = q0 * (__expf(em.x) * scale);
            qs1 = q1 * (__expf(em.y) * scale);
            e_acc += e;
        } else {
            qs0 = oldp.x; qs1 = oldp.y;
        }

        *(float2*)&sP[cur ^ 1][g][jo][k0] = make_float2(qs0, qs1);

        float pr = qs0 + qs1;
        pr += __shfl_xor_sync(0xffffffffu, pr, 1);
        pr += __shfl_xor_sync(0xffffffffu, pr, 2);
        pr += __shfl_xor_sync(0xffffffffu, pr, 4);
        pr += __shfl_xor_sync(0xffffffffu, pr, 8);
        if (kidx == 0) sS[cur ^ 1][g][jo][wg] = pr;

        barg(g);              // group-private barrier: other group overlaps our tail
        cur ^= 1;
    }

    // ---- finalize: logZ = e_acc*ln2 + log( sum_k p~[k]*exp(end[k]) ) ----
    {
        const float2 en = *(const float2*)(end_t + k0);
        const float2 pv = *(const float2*)&sP[cur][g][jo][k0];
        float z = pv.x * __expf(en.x) + pv.y * __expf(en.y);
        z += __shfl_xor_sync(0xffffffffu, z, 1);
        z += __shfl_xor_sync(0xffffffffu, z, 2);
        z += __shfl_xor_sync(0xffffffffu, z, 4);
        z += __shfl_xor_sync(0xffffffffu, z, 8);
        if (kidx == 0) sS[0][g][jo][wg] = z;
        barg(g);
        if (wg == 0 && kidx == 0) {
            float tot = sS[0][g][jo][0] + sS[0][g][jo][1]
                      + sS[0][g][jo][2] + sS[0][g][jo][3];
            g_logZ[bg] = (float)e_acc * LN2F + logf(tot);
        }
    }
}

// Numerator: one block per batch.
__global__ void crf_num(const float* __restrict__ emissions,
                        const int*   __restrict__ tags,
                        const int*   __restrict__ mask,
                        const float* __restrict__ start_t,
                        const float* __restrict__ end_t,
                        const float* __restrict__ trans)
{
    const int b   = blockIdx.x;
    const int tid = threadIdx.x;
    __shared__ float rf[256];
    __shared__ int   ri[256];

    float loc = 0.f;
    int   cnt = 0;
    for (int i = tid; i < LL; i += 256) {
        int tag = tags[i * BB + b];
        int m   = mask[i * BB + b];
        if (m) {
            loc += emissions[((size_t)i * BB + b) * TT + tag];
            cnt++;
            if (i > 0) loc += trans[tags[(i - 1) * BB + b] * TT + tag];
        }
        if (i == 0) loc += start_t[tag];
    }
    rf[tid] = loc; ri[tid] = cnt;
    __syncthreads();
    #pragma unroll
    for (int s = 128; s > 0; s >>= 1) {
        if (tid < s) { rf[tid] += rf[tid + s]; ri[tid] += ri[tid + s]; }
        __syncthreads();
    }
    if (tid == 0) {
        int ends = ri[0] - 1;
        if (ends < 0) ends = 0;
        g_num[b] = rf[0] + end_t[tags[ends * BB + b]];
    }
}

__global__ void crf_final(float* __restrict__ out)
{
    __shared__ float r[512];
    const int tid = threadIdx.x;
    r[tid] = g_logZ[tid] - g_num[tid];
    __syncthreads();
    #pragma unroll
    for (int s = 256; s > 0; s >>= 1) {
        if (tid < s) r[tid] += r[tid + s];
        __syncthreads();
    }
    if (tid == 0) out[0] = r[0] * (1.0f / (float)BB);
}

extern "C" void kernel_launch(void* const* d_in, const int* in_sizes, int n_in,
                              void* d_out, int out_size)
{
    const float* emissions = (const float*)d_in[0];
    const int*   tags      = (const int*)d_in[1];
    const int*   mask      = (const int*)d_in[2];
    const float* start_t   = (const float*)d_in[3];
    const float* end_t     = (const float*)d_in[4];
    const float* trans     = (const float*)d_in[5];
    float*       out       = (float*)d_out;

    crf_forward<<<NCTA, NTHREADS>>>(emissions, mask, start_t, end_t, trans);
    crf_num<<<BB, 256>>>(emissions, tags, mask, start_t, end_t, trans);
    crf_final<<<1, BB>>>(out);
}